// round 3
// baseline (speedup 1.0000x reference)
#include <cuda_runtime.h>
#include <cstddef>

// ODE-RNN persistent kernel, vectorized-LDS version.
// T=500, B=4096, IN=32, HID=16, ODE_HIDDEN=50 (padded to 64 = 8 lanes x 8), RK4 x4.
// 8 lanes per row, 4 rows per warp, 16 rows per 128-thread block, 256 blocks.

#define T_STEPS 500
#define BATCH   4096
#define IN_DIM  32
#define HID     16
#define BLK     128
#define ROWS_PER_BLK 16
#define XPITCH  36   // padded x row pitch (floats) for conflict-free group reads

struct __align__(16) SW {
    // W1v[k*96 + lane*12 + m] = W1[lane*8+m][k]  (m<8, j<50; else 0)
    float W1v[HID * 96];
    // b1v[lane*12 + m] = b1[lane*8+m]
    float b1v[96];
    // W2v[(jj*8+lane)*20 + i] = W2[i][lane*8+jj]  (i<16, j<50; else 0)
    float W2v[64 * 20];
    // Wihv[m*96 + lane*12 + c], c:0..5 = {r,z,n}(u1) then {r,z,n}(u2)
    float Wihv[IN_DIM * 96];
    // Whhv[k*96 + lane*12 + c], same c mapping
    float Whhv[HID * 96];
    // x staging: xs[grp*36 + 0..31]
    float xs[ROWS_PER_BLK * XPITCH];
    float ts[T_STEPS];
};

__device__ __forceinline__ float fast_tanh(float v) {
    float e = __expf(2.0f * v);
    return 1.0f - __fdividef(2.0f, e + 1.0f);
}
__device__ __forceinline__ float fast_sig(float v) {
    return __fdividef(1.0f, 1.0f + __expf(-v));
}

// f = W2 * tanh(W1 * y + b1) + b2 ; y replicated on the 8 lanes, result replicated.
__device__ __forceinline__ void ode_f(const SW& s, const float (&b2r)[HID],
                                      const float (&y)[HID], float (&f)[HID], int lane)
{
    const int lo = lane * 12;
    // ---- layer 1: 8 hidden units per lane, 2x float4 accumulators ----
    float4 a0 = *(const float4*)(s.b1v + lo);
    float4 a1 = *(const float4*)(s.b1v + lo + 4);
#pragma unroll
    for (int k = 0; k < HID; k++) {
        const float yk = y[k];
        const float4 w0 = *(const float4*)(s.W1v + k * 96 + lo);
        const float4 w1 = *(const float4*)(s.W1v + k * 96 + lo + 4);
        a0.x = fmaf(yk, w0.x, a0.x); a0.y = fmaf(yk, w0.y, a0.y);
        a0.z = fmaf(yk, w0.z, a0.z); a0.w = fmaf(yk, w0.w, a0.w);
        a1.x = fmaf(yk, w1.x, a1.x); a1.y = fmaf(yk, w1.y, a1.y);
        a1.z = fmaf(yk, w1.z, a1.z); a1.w = fmaf(yk, w1.w, a1.w);
    }
    float z[8];
    z[0] = fast_tanh(a0.x); z[1] = fast_tanh(a0.y);
    z[2] = fast_tanh(a0.z); z[3] = fast_tanh(a0.w);
    z[4] = fast_tanh(a1.x); z[5] = fast_tanh(a1.y);
    z[6] = fast_tanh(a1.z); z[7] = fast_tanh(a1.w);

    // ---- layer 2: per-lane partial over its 8 z's, 16 outputs in 4x float4 ----
    float4 p0 = make_float4(0.f, 0.f, 0.f, 0.f);
    float4 p1 = p0, p2 = p0, p3 = p0;
#pragma unroll
    for (int jj = 0; jj < 8; jj++) {
        const float zz = z[jj];
        const float* wr = s.W2v + (jj * 8 + lane) * 20;
        const float4 w0 = *(const float4*)(wr);
        const float4 w1 = *(const float4*)(wr + 4);
        const float4 w2 = *(const float4*)(wr + 8);
        const float4 w3 = *(const float4*)(wr + 12);
        p0.x = fmaf(zz, w0.x, p0.x); p0.y = fmaf(zz, w0.y, p0.y);
        p0.z = fmaf(zz, w0.z, p0.z); p0.w = fmaf(zz, w0.w, p0.w);
        p1.x = fmaf(zz, w1.x, p1.x); p1.y = fmaf(zz, w1.y, p1.y);
        p1.z = fmaf(zz, w1.z, p1.z); p1.w = fmaf(zz, w1.w, p1.w);
        p2.x = fmaf(zz, w2.x, p2.x); p2.y = fmaf(zz, w2.y, p2.y);
        p2.z = fmaf(zz, w2.z, p2.z); p2.w = fmaf(zz, w2.w, p2.w);
        p3.x = fmaf(zz, w3.x, p3.x); p3.y = fmaf(zz, w3.y, p3.y);
        p3.z = fmaf(zz, w3.z, p3.z); p3.w = fmaf(zz, w3.w, p3.w);
    }
    float pf[HID] = { p0.x, p0.y, p0.z, p0.w, p1.x, p1.y, p1.z, p1.w,
                      p2.x, p2.y, p2.z, p2.w, p3.x, p3.y, p3.z, p3.w };
    // ---- all-reduce across the 8 lanes ----
#pragma unroll
    for (int i = 0; i < HID; i++) {
        float v = pf[i];
        v += __shfl_xor_sync(0xffffffffu, v, 1, 8);
        v += __shfl_xor_sync(0xffffffffu, v, 2, 8);
        v += __shfl_xor_sync(0xffffffffu, v, 4, 8);
        f[i] = v + b2r[i];
    }
}

__global__ void __launch_bounds__(BLK) odernn_kernel(
    const float* __restrict__ x,   const float* __restrict__ t,
    const float* __restrict__ W1,  const float* __restrict__ b1,
    const float* __restrict__ W2,  const float* __restrict__ b2,
    const float* __restrict__ Wih, const float* __restrict__ bih,
    const float* __restrict__ Whh, const float* __restrict__ bhh,
    const float* __restrict__ Wout, const float* __restrict__ bout,
    float* __restrict__ out)
{
    __shared__ SW s;
    const int tid = threadIdx.x;

    // ---- stage weights into swizzled shared layouts ----
    for (int idx = tid; idx < HID * 96; idx += BLK) {
        int k = idx / 96, r = idx % 96, l = r / 12, m = r % 12;
        int j = l * 8 + m;
        s.W1v[idx] = (m < 8 && j < 50) ? W1[j * HID + k] : 0.0f;
    }
    for (int idx = tid; idx < 96; idx += BLK) {
        int l = idx / 12, m = idx % 12;
        int j = l * 8 + m;
        s.b1v[idx] = (m < 8 && j < 50) ? b1[j] : 0.0f;
    }
    for (int idx = tid; idx < 64 * 20; idx += BLK) {
        int rr = idx / 20, i = idx % 20, jj = rr / 8, l = rr % 8;
        int j = l * 8 + jj;
        s.W2v[idx] = (i < HID && j < 50) ? W2[i * 50 + j] : 0.0f;
    }
    for (int idx = tid; idx < IN_DIM * 96; idx += BLK) {
        int m = idx / 96, r = idx % 96, l = r / 12, c = r % 12;
        float v = 0.0f;
        if (c < 6) {
            int u = (c < 3) ? l : (l + 8);
            int e = (c < 3) ? c : (c - 3);
            v = Wih[(e * HID + u) * IN_DIM + m];
        }
        s.Wihv[idx] = v;
    }
    for (int idx = tid; idx < HID * 96; idx += BLK) {
        int k = idx / 96, r = idx % 96, l = r / 12, c = r % 12;
        float v = 0.0f;
        if (c < 6) {
            int u = (c < 3) ? l : (l + 8);
            int e = (c < 3) ? c : (c - 3);
            v = Whh[(e * HID + u) * HID + k];
        }
        s.Whhv[idx] = v;
    }
    for (int idx = tid; idx < T_STEPS; idx += BLK) s.ts[idx] = t[idx];
    __syncthreads();

    const int lane = tid & 7;
    const int grp  = tid >> 3;              // 0..15
    const int row  = blockIdx.x * ROWS_PER_BLK + grp;
    const int u1 = lane, u2 = lane + 8;

    // ---- lane-resident constants ----
    float b2r[HID];
#pragma unroll
    for (int i = 0; i < HID; i++) b2r[i] = b2[i];
    const float bi0 = bih[u1], bi1 = bih[16 + u1], bi2 = bih[32 + u1];
    const float bi3 = bih[u2], bi4 = bih[16 + u2], bi5 = bih[32 + u2];
    const float bh0 = bhh[u1], bh1 = bhh[16 + u1], bh2 = bhh[32 + u1];
    const float bh3 = bhh[u2], bh4 = bhh[16 + u2], bh5 = bhh[32 + u2];
    const float wo1 = Wout[u1], wo2 = Wout[u2];
    const float bo  = bout[0];

    float h[HID], y[HID], acc[HID], f[HID];
#pragma unroll
    for (int k = 0; k < HID; k++) h[k] = 0.0f;

    float* xslot = s.xs + grp * XPITCH;

#pragma unroll 1
    for (int i = 0; i < T_STEPS - 1; ++i) {
        // issue this step's x load early (consumed after RK4 via shared)
        const float4 gx = __ldg((const float4*)(x + ((size_t)i * BATCH + row) * IN_DIM) + lane);

        const float dt  = (s.ts[i + 1] - s.ts[i]) * 0.25f;
        const float hdt = 0.5f * dt;
        const float dt6 = dt / 6.0f;

        // ---- 4 RK4 substeps ----
#pragma unroll 1
        for (int ss = 0; ss < 4; ss++) {
#pragma unroll
            for (int k = 0; k < HID; k++) y[k] = h[k];
#pragma unroll 1
            for (int e = 0; e < 4; e++) {
                ode_f(s, b2r, y, f, lane);
                const float w  = (e == 0 || e == 3) ? 1.0f : 2.0f;
                const float cy = (e == 2) ? dt : hdt;
                if (e == 0) {
#pragma unroll
                    for (int k = 0; k < HID; k++) acc[k] = f[k];
                } else {
#pragma unroll
                    for (int k = 0; k < HID; k++) acc[k] = fmaf(w, f[k], acc[k]);
                }
                if (e < 3) {
#pragma unroll
                    for (int k = 0; k < HID; k++) y[k] = fmaf(cy, f[k], h[k]);
                }
            }
#pragma unroll
            for (int k = 0; k < HID; k++) h[k] = fmaf(dt6, acc[k], h[k]);
        }

        // ---- park x row in shared, then GRU reads it vectorized ----
        __syncwarp();
        *(float4*)(xslot + lane * 4) = gx;
        __syncwarp();

        // ---- GRU cell (r, z, n). Lane computes units u1, u2. ----
        float g0 = bi0, g1 = bi1, g2 = bi2, g3 = bi3, g4 = bi4, g5 = bi5;
        float q0 = bh0, q1 = bh1, q2 = bh2, q3 = bh3, q4 = bh4, q5 = bh5;
        const int lo = lane * 12;
#pragma unroll
        for (int qv = 0; qv < 8; qv++) {
            const float4 xv = *(const float4*)(xslot + qv * 4);
            const float xm0 = xv.x, xm1 = xv.y, xm2 = xv.z, xm3 = xv.w;
            const int m0 = qv * 4;
#pragma unroll
            for (int c = 0; c < 4; c++) {
                const float xm = (c == 0) ? xm0 : (c == 1) ? xm1 : (c == 2) ? xm2 : xm3;
                const float* wp = s.Wihv + (m0 + c) * 96 + lo;
                const float4 v0 = *(const float4*)(wp);
                const float4 v1 = *(const float4*)(wp + 4);
                g0 = fmaf(xm, v0.x, g0); g1 = fmaf(xm, v0.y, g1);
                g2 = fmaf(xm, v0.z, g2); g3 = fmaf(xm, v0.w, g3);
                g4 = fmaf(xm, v1.x, g4); g5 = fmaf(xm, v1.y, g5);
            }
        }
        float hu1 = 0.0f, hu2 = 0.0f;
#pragma unroll
        for (int k = 0; k < HID; k++) {
            const float hk = h[k];
            if (k < 8)  { if (k == u1) hu1 = hk; }
            else        { if (k == u2) hu2 = hk; }
            const float* wp = s.Whhv + k * 96 + lo;
            const float4 v0 = *(const float4*)(wp);
            const float4 v1 = *(const float4*)(wp + 4);
            q0 = fmaf(hk, v0.x, q0); q1 = fmaf(hk, v0.y, q1);
            q2 = fmaf(hk, v0.z, q2); q3 = fmaf(hk, v0.w, q3);
            q4 = fmaf(hk, v1.x, q4); q5 = fmaf(hk, v1.y, q5);
        }
        const float r1 = fast_sig(g0 + q0);
        const float z1 = fast_sig(g1 + q1);
        const float n1 = fast_tanh(fmaf(r1, q2, g2));
        const float hn1 = fmaf(z1, hu1 - n1, n1);
        const float r2 = fast_sig(g3 + q3);
        const float z2 = fast_sig(g4 + q4);
        const float n2 = fast_tanh(fmaf(r2, q5, g5));
        const float hn2 = fmaf(z2, hu2 - n2, n2);

        // ---- output head ----
        float po = hn1 * wo1 + hn2 * wo2;
        po += __shfl_xor_sync(0xffffffffu, po, 1, 8);
        po += __shfl_xor_sync(0xffffffffu, po, 2, 8);
        po += __shfl_xor_sync(0xffffffffu, po, 4, 8);
        if (lane == 0) out[(size_t)i * BATCH + row] = po + bo;

        // ---- replicate new hidden state to all 8 lanes ----
#pragma unroll
        for (int k = 0; k < 8; k++) {
            h[k]     = __shfl_sync(0xffffffffu, hn1, k, 8);
            h[k + 8] = __shfl_sync(0xffffffffu, hn2, k, 8);
        }
    }
}

extern "C" void kernel_launch(void* const* d_in, const int* in_sizes, int n_in,
                              void* d_out, int out_size) {
    (void)in_sizes; (void)n_in; (void)out_size;
    const float* x    = (const float*)d_in[0];
    const float* t    = (const float*)d_in[1];
    const float* W1   = (const float*)d_in[2];
    const float* b1   = (const float*)d_in[3];
    const float* W2   = (const float*)d_in[4];
    const float* b2   = (const float*)d_in[5];
    const float* Wih  = (const float*)d_in[6];
    const float* bih  = (const float*)d_in[7];
    const float* Whh  = (const float*)d_in[8];
    const float* bhh  = (const float*)d_in[9];
    const float* Wout = (const float*)d_in[10];
    const float* bout = (const float*)d_in[11];
    float* out = (float*)d_out;

    dim3 grid(BATCH / ROWS_PER_BLK);
    dim3 block(BLK);
    odernn_kernel<<<grid, block>>>(x, t, W1, b1, W2, b2, Wih, bih, Whh, bhh, Wout, bout, out);
}

// round 4
// speedup vs baseline: 1.2425x; 1.2425x over previous
#include <cuda_runtime.h>
#include <cstddef>

// ODE-RNN persistent kernel — distributed-state version.
// T=500, B=4096, IN=32, HID=16, ODE_HIDDEN=50 (pad 64), RK4 x4.
// 8 lanes per row; lane owns components (2*lane, 2*lane+1) of distributed vectors.
// 4 rows per warp, 16 rows per 128-thread block, 256 blocks.

#define T_STEPS 500
#define BATCH   4096
#define IN_DIM  32
#define HID     16
#define BLK     128
#define ROWS_PER_BLK 16
#define XPITCH  36

struct __align__(16) SW {
    float W1v[HID * 96];     // [k*96 + l*12 + m] = W1[l*8+m][k]  (m<8, j<50)
    float b1v[96];           // [l*12 + m] = b1[l*8+m]
    float W2v[64 * 20];      // [(jj*8+l)*20 + i] = W2[i][l*8+jj]
    float Wihv[IN_DIM * 96]; // [m*96 + l*12 + c] c: e=c%3 (r,z,n), unit=2l+c/3
    float Whhv[HID * 96];    // [k*96 + l*12 + c] same mapping
    float biasv[96];         // [l*12 + c]: c<6 -> bih, c>=6 -> bhh (same gate map)
    float b2v[16];
    float woutv[16];
    float xs[ROWS_PER_BLK * XPITCH];
    float ts[T_STEPS];
};

__device__ __forceinline__ float fast_tanh(float v) {
    float e = __expf(2.0f * v);
    return 1.0f - __fdividef(2.0f, e + 1.0f);
}
__device__ __forceinline__ float fast_sig(float v) {
    return __fdividef(1.0f, 1.0f + __expf(-v));
}

#define FULLM 0xffffffffu

// reduce-scatter: pf[16] partials (per lane) -> lane gets sums of comps 2l, 2l+1
__device__ __forceinline__ void reduce_scatter16(const float (&pf)[16], int lane,
                                                 float& r0, float& r1) {
    const bool b4 = (lane & 4) != 0;
    float v8[8];
#pragma unroll
    for (int r = 0; r < 8; r++) {
        float send = b4 ? pf[r] : pf[r + 8];
        float keep = b4 ? pf[r + 8] : pf[r];
        v8[r] = keep + __shfl_xor_sync(FULLM, send, 4, 8);
    }
    const bool b2 = (lane & 2) != 0;
    float v4[4];
#pragma unroll
    for (int r = 0; r < 4; r++) {
        float send = b2 ? v8[r] : v8[r + 4];
        float keep = b2 ? v8[r + 4] : v8[r];
        v4[r] = keep + __shfl_xor_sync(FULLM, send, 2, 8);
    }
    const bool b1 = (lane & 1) != 0;
    float s0 = b1 ? v4[0] : v4[2];
    float k0 = b1 ? v4[2] : v4[0];
    float s1 = b1 ? v4[1] : v4[3];
    float k1 = b1 ? v4[3] : v4[1];
    r0 = k0 + __shfl_xor_sync(FULLM, s0, 1, 8);
    r1 = k1 + __shfl_xor_sync(FULLM, s1, 1, 8);
}

// allgather: lane's (a0,a1) = comps (2l, 2l+1) -> o[16] replicated on all 8 lanes
__device__ __forceinline__ void allgather16(float a0, float a1, int lane, float (&o)[16]) {
    const bool b1 = (lane & 1) != 0;
    float c0 = __shfl_xor_sync(FULLM, a0, 1, 8);
    float c1 = __shfl_xor_sync(FULLM, a1, 1, 8);
    float g4_0 = b1 ? c0 : a0;
    float g4_1 = b1 ? c1 : a1;
    float g4_2 = b1 ? a0 : c0;
    float g4_3 = b1 ? a1 : c1;
    const bool b2 = (lane & 2) != 0;
    float d0 = __shfl_xor_sync(FULLM, g4_0, 2, 8);
    float d1 = __shfl_xor_sync(FULLM, g4_1, 2, 8);
    float d2 = __shfl_xor_sync(FULLM, g4_2, 2, 8);
    float d3 = __shfl_xor_sync(FULLM, g4_3, 2, 8);
    float g8[8];
    g8[0] = b2 ? d0 : g4_0; g8[1] = b2 ? d1 : g4_1;
    g8[2] = b2 ? d2 : g4_2; g8[3] = b2 ? d3 : g4_3;
    g8[4] = b2 ? g4_0 : d0; g8[5] = b2 ? g4_1 : d1;
    g8[6] = b2 ? g4_2 : d2; g8[7] = b2 ? g4_3 : d3;
    const bool b4 = (lane & 4) != 0;
#pragma unroll
    for (int r = 0; r < 8; r++) {
        float e = __shfl_xor_sync(FULLM, g8[r], 4, 8);
        o[r]     = b4 ? e : g8[r];
        o[r + 8] = b4 ? g8[r] : e;
    }
}

// pf[16] = per-lane partials of W2 * tanh(W1*y + b1); y replicated in regs.
__device__ __forceinline__ void ode_partials(const SW& s, const float (&y)[HID],
                                             float (&pf)[16], int lo) {
    float4 a0 = *(const float4*)(s.b1v + lo);
    float4 a1 = *(const float4*)(s.b1v + lo + 4);
#pragma unroll
    for (int k = 0; k < HID; k++) {
        const float yk = y[k];
        const float4 w0 = *(const float4*)(s.W1v + k * 96 + lo);
        const float4 w1 = *(const float4*)(s.W1v + k * 96 + lo + 4);
        a0.x = fmaf(yk, w0.x, a0.x); a0.y = fmaf(yk, w0.y, a0.y);
        a0.z = fmaf(yk, w0.z, a0.z); a0.w = fmaf(yk, w0.w, a0.w);
        a1.x = fmaf(yk, w1.x, a1.x); a1.y = fmaf(yk, w1.y, a1.y);
        a1.z = fmaf(yk, w1.z, a1.z); a1.w = fmaf(yk, w1.w, a1.w);
    }
    float z[8];
    z[0] = fast_tanh(a0.x); z[1] = fast_tanh(a0.y);
    z[2] = fast_tanh(a0.z); z[3] = fast_tanh(a0.w);
    z[4] = fast_tanh(a1.x); z[5] = fast_tanh(a1.y);
    z[6] = fast_tanh(a1.z); z[7] = fast_tanh(a1.w);
#pragma unroll
    for (int i = 0; i < 16; i++) pf[i] = 0.0f;
#pragma unroll
    for (int jj = 0; jj < 8; jj++) {
        const float zz = z[jj];
        const float* wr = s.W2v + (jj * 8) * 20 + (lo / 12) * 20;  // (jj*8+lane)*20
        const float4 w0 = *(const float4*)(wr);
        const float4 w1 = *(const float4*)(wr + 4);
        const float4 w2 = *(const float4*)(wr + 8);
        const float4 w3 = *(const float4*)(wr + 12);
        pf[0]  = fmaf(zz, w0.x, pf[0]);  pf[1]  = fmaf(zz, w0.y, pf[1]);
        pf[2]  = fmaf(zz, w0.z, pf[2]);  pf[3]  = fmaf(zz, w0.w, pf[3]);
        pf[4]  = fmaf(zz, w1.x, pf[4]);  pf[5]  = fmaf(zz, w1.y, pf[5]);
        pf[6]  = fmaf(zz, w1.z, pf[6]);  pf[7]  = fmaf(zz, w1.w, pf[7]);
        pf[8]  = fmaf(zz, w2.x, pf[8]);  pf[9]  = fmaf(zz, w2.y, pf[9]);
        pf[10] = fmaf(zz, w2.z, pf[10]); pf[11] = fmaf(zz, w2.w, pf[11]);
        pf[12] = fmaf(zz, w3.x, pf[12]); pf[13] = fmaf(zz, w3.y, pf[13]);
        pf[14] = fmaf(zz, w3.z, pf[14]); pf[15] = fmaf(zz, w3.w, pf[15]);
    }
}

__global__ void __launch_bounds__(BLK) odernn_kernel(
    const float* __restrict__ x,   const float* __restrict__ t,
    const float* __restrict__ W1,  const float* __restrict__ b1,
    const float* __restrict__ W2,  const float* __restrict__ b2,
    const float* __restrict__ Wih, const float* __restrict__ bih,
    const float* __restrict__ Whh, const float* __restrict__ bhh,
    const float* __restrict__ Wout, const float* __restrict__ bout,
    float* __restrict__ out)
{
    __shared__ SW s;
    const int tid = threadIdx.x;

    // ---- stage weights ----
    for (int idx = tid; idx < HID * 96; idx += BLK) {
        int k = idx / 96, r = idx % 96, l = r / 12, m = r % 12;
        int j = l * 8 + m;
        s.W1v[idx] = (m < 8 && j < 50) ? W1[j * HID + k] : 0.0f;
    }
    for (int idx = tid; idx < 96; idx += BLK) {
        int l = idx / 12, m = idx % 12;
        int j = l * 8 + m;
        s.b1v[idx] = (m < 8 && j < 50) ? b1[j] : 0.0f;
    }
    for (int idx = tid; idx < 64 * 20; idx += BLK) {
        int rr = idx / 20, i = idx % 20, jj = rr / 8, l = rr % 8;
        int j = l * 8 + jj;
        s.W2v[idx] = (i < HID && j < 50) ? W2[i * 50 + j] : 0.0f;
    }
    for (int idx = tid; idx < IN_DIM * 96; idx += BLK) {
        int m = idx / 96, r = idx % 96, l = r / 12, c = r % 12;
        float v = 0.0f;
        if (c < 6) {
            int e = c % 3, du = c / 3;
            v = Wih[(e * HID + 2 * l + du) * IN_DIM + m];
        }
        s.Wihv[idx] = v;
    }
    for (int idx = tid; idx < HID * 96; idx += BLK) {
        int k = idx / 96, r = idx % 96, l = r / 12, c = r % 12;
        float v = 0.0f;
        if (c < 6) {
            int e = c % 3, du = c / 3;
            v = Whh[(e * HID + 2 * l + du) * HID + k];
        }
        s.Whhv[idx] = v;
    }
    for (int idx = tid; idx < 96; idx += BLK) {
        int l = idx / 12, c = idx % 12;
        float v;
        if (c < 6) { int e = c % 3, du = c / 3; v = bih[e * HID + 2 * l + du]; }
        else       { int cc = c - 6; int e = cc % 3, du = cc / 3; v = bhh[e * HID + 2 * l + du]; }
        s.biasv[idx] = v;
    }
    for (int idx = tid; idx < HID; idx += BLK) { s.b2v[idx] = b2[idx]; s.woutv[idx] = Wout[idx]; }
    for (int idx = tid; idx < T_STEPS; idx += BLK) s.ts[idx] = t[idx];
    __syncthreads();

    const int lane = tid & 7;
    const int grp  = tid >> 3;
    const int row  = blockIdx.x * ROWS_PER_BLK + grp;
    const int lo   = lane * 12;

    // lane-owned small constants
    const float2 b2own = *(const float2*)(s.b2v + 2 * lane);    // b2[2l], b2[2l+1]
    const float2 woown = *(const float2*)(s.woutv + 2 * lane);
    const float  bo    = bout[0];

    float h[HID];
#pragma unroll
    for (int k = 0; k < HID; k++) h[k] = 0.0f;
    float hown0 = 0.0f, hown1 = 0.0f;   // distributed shadow of h[2l], h[2l+1]

    float* xslot = s.xs + grp * XPITCH;

#pragma unroll 1
    for (int i = 0; i < T_STEPS - 1; ++i) {
        const float4 gx = __ldg((const float4*)(x + ((size_t)i * BATCH + row) * IN_DIM) + lane);

        const float dt  = (s.ts[i + 1] - s.ts[i]) * 0.25f;
        const float hdt = 0.5f * dt;
        const float dt6 = dt / 6.0f;

        // ---- 4 RK4 substeps ----
#pragma unroll 1
        for (int ss = 0; ss < 4; ss++) {
            float y[HID];
#pragma unroll
            for (int k = 0; k < HID; k++) y[k] = h[k];
            float acc0 = 0.0f, acc1 = 0.0f;
#pragma unroll 1
            for (int e = 0; e < 4; e++) {
                float pf[16];
                ode_partials(s, y, pf, lo);
                float f0, f1;
                reduce_scatter16(pf, lane, f0, f1);
                f0 += b2own.x;
                f1 += b2own.y;
                const float w = (e == 0 || e == 3) ? 1.0f : 2.0f;
                acc0 = fmaf(w, f0, acc0);
                acc1 = fmaf(w, f1, acc1);
                if (e < 3) {
                    const float cy = (e == 2) ? dt : hdt;
                    float frep[HID];
                    allgather16(f0, f1, lane, frep);
#pragma unroll
                    for (int k = 0; k < HID; k++) y[k] = fmaf(cy, frep[k], h[k]);
                }
            }
            // h += dt6 * acc
            float accr[HID];
            allgather16(acc0, acc1, lane, accr);
#pragma unroll
            for (int k = 0; k < HID; k++) h[k] = fmaf(dt6, accr[k], h[k]);
            hown0 = fmaf(dt6, acc0, hown0);
            hown1 = fmaf(dt6, acc1, hown1);
        }

        // ---- park x row; GRU reads it vectorized ----
        __syncwarp();                       // prior GRU reads complete
        *(float4*)(xslot + lane * 4) = gx;
        __syncwarp();

        // ---- GRU cell. Lane computes units u0=2l, u1=2l+1. ----
        const float4 bq0 = *(const float4*)(s.biasv + lo);
        const float4 bq1 = *(const float4*)(s.biasv + lo + 4);
        const float4 bq2 = *(const float4*)(s.biasv + lo + 8);
        float g0 = bq0.x, g1 = bq0.y, g2 = bq0.z, g3 = bq0.w, g4 = bq1.x, g5 = bq1.y;
        float qa0 = bq1.z, qa1 = bq1.w, qa2 = bq2.x, qa3 = bq2.y, qa4 = bq2.z, qa5 = bq2.w;

#pragma unroll
        for (int qv = 0; qv < 8; qv++) {
            const float4 xv = *(const float4*)(xslot + qv * 4);
#pragma unroll
            for (int c = 0; c < 4; c++) {
                const float xm = (c == 0) ? xv.x : (c == 1) ? xv.y : (c == 2) ? xv.z : xv.w;
                const float* wp = s.Wihv + (qv * 4 + c) * 96 + lo;
                const float4 v0 = *(const float4*)(wp);
                const float2 v1 = *(const float2*)(wp + 4);
                g0 = fmaf(xm, v0.x, g0); g1 = fmaf(xm, v0.y, g1);
                g2 = fmaf(xm, v0.z, g2); g3 = fmaf(xm, v0.w, g3);
                g4 = fmaf(xm, v1.x, g4); g5 = fmaf(xm, v1.y, g5);
            }
        }
#pragma unroll
        for (int k = 0; k < HID; k++) {
            const float hk = h[k];
            const float* wp = s.Whhv + k * 96 + lo;
            const float4 v0 = *(const float4*)(wp);
            const float2 v1 = *(const float2*)(wp + 4);
            qa0 = fmaf(hk, v0.x, qa0); qa1 = fmaf(hk, v0.y, qa1);
            qa2 = fmaf(hk, v0.z, qa2); qa3 = fmaf(hk, v0.w, qa3);
            qa4 = fmaf(hk, v1.x, qa4); qa5 = fmaf(hk, v1.y, qa5);
        }
        const float r0 = fast_sig(g0 + qa0);
        const float z0 = fast_sig(g1 + qa1);
        const float n0 = fast_tanh(fmaf(r0, qa2, g2));
        const float hn0 = fmaf(z0, hown0 - n0, n0);
        const float r1 = fast_sig(g3 + qa3);
        const float z1 = fast_sig(g4 + qa4);
        const float n1 = fast_tanh(fmaf(r1, qa5, g5));
        const float hn1 = fmaf(z1, hown1 - n1, n1);

        // ---- output head ----
        float po = hn0 * woown.x + hn1 * woown.y;
        po += __shfl_xor_sync(FULLM, po, 1, 8);
        po += __shfl_xor_sync(FULLM, po, 2, 8);
        po += __shfl_xor_sync(FULLM, po, 4, 8);
        if (lane == 0) out[(size_t)i * BATCH + row] = po + bo;

        // ---- new hidden state ----
        hown0 = hn0;
        hown1 = hn1;
        allgather16(hn0, hn1, lane, h);
    }
}

extern "C" void kernel_launch(void* const* d_in, const int* in_sizes, int n_in,
                              void* d_out, int out_size) {
    (void)in_sizes; (void)n_in; (void)out_size;
    const float* x    = (const float*)d_in[0];
    const float* t    = (const float*)d_in[1];
    const float* W1   = (const float*)d_in[2];
    const float* b1   = (const float*)d_in[3];
    const float* W2   = (const float*)d_in[4];
    const float* b2   = (const float*)d_in[5];
    const float* Wih  = (const float*)d_in[6];
    const float* bih  = (const float*)d_in[7];
    const float* Whh  = (const float*)d_in[8];
    const float* bhh  = (const float*)d_in[9];
    const float* Wout = (const float*)d_in[10];
    const float* bout = (const float*)d_in[11];
    float* out = (float*)d_out;

    dim3 grid(BATCH / ROWS_PER_BLK);
    dim3 block(BLK);
    odernn_kernel<<<grid, block>>>(x, t, W1, b1, W2, b2, Wih, bih, Whh, bhh, Wout, bout, out);
}

// round 5
// speedup vs baseline: 1.4869x; 1.1967x over previous
#include <cuda_runtime.h>
#include <cstddef>

// ODE-RNN persistent kernel — shared-state, 16 lanes/row.
// T=500, B=4096, IN=32, HID=16, ODE_HIDDEN=50 (pad 64), RK4 x4.
// Lane owns hidden comp c=lane and ODE-hidden j=4c..4c+3. State in shared; no shuffles in RK4.
// 128 threads = 8 rows per block, grid 512 -> single wave at 4 blocks/SM.

#define T_STEPS 500
#define BATCH   4096
#define IN_DIM  32
#define HID     16
#define BLK     128
#define ROWS_PER_BLK 8

__device__ __forceinline__ float tanh_apx(float x) {
    float r;
    asm("tanh.approx.f32 %0, %1;" : "=f"(r) : "f"(x));
    return r;
}
__device__ __forceinline__ float fast_tanh(float v) {      // precise (GRU n-gate)
    float e = __expf(2.0f * v);
    return 1.0f - __fdividef(2.0f, e + 1.0f);
}
__device__ __forceinline__ float fast_sig(float v) {       // precise (GRU r,z gates)
    return __fdividef(1.0f, 1.0f + __expf(-v));
}

#define FULLM 0xffffffffu

__global__ void __launch_bounds__(BLK, 4) odernn_kernel(
    const float* __restrict__ x,   const float* __restrict__ t,
    const float* __restrict__ W1,  const float* __restrict__ b1,
    const float* __restrict__ W2,  const float* __restrict__ b2,
    const float* __restrict__ Wih, const float* __restrict__ bih,
    const float* __restrict__ Whh, const float* __restrict__ bhh,
    const float* __restrict__ Wout, const float* __restrict__ bout,
    float* __restrict__ out)
{
    // ---- shared arrays (all pitches chosen conflict-free / 16B-aligned) ----
    __shared__ float W1L[16 * 68];    // [k*68 + j] = W1[j][k], j<50 else 0 (j=0..63)
    __shared__ float b1L[64];         // b1[j] or 0
    __shared__ float W2c[16 * 68];    // [c*68 + j] = W2[c][j], j<50 else 0
    __shared__ float Wihc[16 * 108];  // [u*108 + e*36 + m] = W_ih[e*16+u][m]
    __shared__ float Whhc[16 * 60];   // [u*60  + e*20 + k] = W_hh[e*16+u][k]
    __shared__ float ys[ROWS_PER_BLK * 20];   // state y/h per row
    __shared__ float zs[ROWS_PER_BLK * 68];   // layer-1 activations per row
    __shared__ float xs[ROWS_PER_BLK * 36];   // x row staging
    __shared__ float ts[T_STEPS];

    const int tid = threadIdx.x;

    // ---- stage weights ----
    for (int idx = tid; idx < 16 * 68; idx += BLK) {
        int k = idx / 68, j = idx % 68;
        W1L[idx] = (j < 50) ? W1[j * HID + k] : 0.0f;
    }
    for (int idx = tid; idx < 64; idx += BLK)
        b1L[idx] = (idx < 50) ? b1[idx] : 0.0f;
    for (int idx = tid; idx < 16 * 68; idx += BLK) {
        int c = idx / 68, j = idx % 68;
        W2c[idx] = (j < 50) ? W2[c * 50 + j] : 0.0f;
    }
    for (int idx = tid; idx < 16 * 108; idx += BLK) {
        int u = idx / 108, r = idx % 108, e = r / 36, m = r % 36;
        Wihc[idx] = (m < 32) ? Wih[(e * HID + u) * IN_DIM + m] : 0.0f;
    }
    for (int idx = tid; idx < 16 * 60; idx += BLK) {
        int u = idx / 60, r = idx % 60, e = r / 20, k = r % 20;
        Whhc[idx] = (k < 16) ? Whh[(e * HID + u) * HID + k] : 0.0f;
    }
    for (int idx = tid; idx < T_STEPS; idx += BLK) ts[idx] = t[idx];

    const int lane = tid & 15;          // hidden comp / GRU unit this lane owns
    const int grp  = tid >> 4;          // 0..7 : row within block
    const int row  = blockIdx.x * ROWS_PER_BLK + grp;

    // ---- per-lane constants (from global; once) ----
    const float b2own   = b2[lane];
    const float woown   = Wout[lane];
    const float bo      = bout[0];
    const float bihr = bih[lane], bihz = bih[16 + lane], bihn = bih[32 + lane];
    const float bhhr = bhh[lane], bhhz = bhh[16 + lane], bhhn = bhh[32 + lane];

    float* const ysg = ys + grp * 20;
    float* const zsg = zs + grp * 68;
    float* const xsg = xs + grp * 36;

    ysg[lane] = 0.0f;                   // h0 = 0
    float hown = 0.0f;
    __syncthreads();                    // staging + state init visible

    const float4 b1own = *(const float4*)(b1L + lane * 4);

#pragma unroll 1
    for (int i = 0; i < T_STEPS - 1; ++i) {
        // stage this step's x row (visible to GRU via the eval syncwarps)
        const float2 gx = __ldg((const float2*)(x + ((size_t)i * BATCH + row) * IN_DIM) + lane);
        *(float2*)(xsg + 2 * lane) = gx;

        const float dtq = (ts[i + 1] - ts[i]) * 0.25f;  // substep dt
        const float hdt = 0.5f * dtq;
        const float dt6 = dtq * (1.0f / 6.0f);

#pragma unroll 1
        for (int ss = 0; ss < 4; ss++) {
            float acc = 0.0f;
#pragma unroll 1
            for (int e = 0; e < 4; e++) {
                // ---- read y (replicated, broadcast loads) ----
                float ya[16];
                *(float4*)(ya + 0)  = *(const float4*)(ysg + 0);
                *(float4*)(ya + 4)  = *(const float4*)(ysg + 4);
                *(float4*)(ya + 8)  = *(const float4*)(ysg + 8);
                *(float4*)(ya + 12) = *(const float4*)(ysg + 12);

                // ---- layer 1: lane's 4 hidden units ----
                float4 a = b1own;
#pragma unroll
                for (int k = 0; k < 16; k++) {
                    const float yk = ya[k];
                    const float4 w = *(const float4*)(&W1L[k * 68 + lane * 4]);
                    a.x = fmaf(yk, w.x, a.x);
                    a.y = fmaf(yk, w.y, a.y);
                    a.z = fmaf(yk, w.z, a.z);
                    a.w = fmaf(yk, w.w, a.w);
                }
                float4 zq;
                zq.x = tanh_apx(a.x); zq.y = tanh_apx(a.y);
                zq.z = tanh_apx(a.z); zq.w = tanh_apx(a.w);
                *(float4*)(zsg + lane * 4) = zq;
                __syncwarp();

                // ---- layer 2: lane's output comp over all 64 z ----
                float p0 = 0.f, p1 = 0.f, p2 = 0.f, p3 = 0.f;
#pragma unroll
                for (int jc = 0; jc < 16; jc++) {
                    const float4 z4 = *(const float4*)(zsg + jc * 4);
                    const float4 w4 = *(const float4*)(&W2c[lane * 68 + jc * 4]);
                    p0 = fmaf(z4.x, w4.x, p0);
                    p1 = fmaf(z4.y, w4.y, p1);
                    p2 = fmaf(z4.z, w4.z, p2);
                    p3 = fmaf(z4.w, w4.w, p3);
                }
                const float f = ((p0 + p1) + (p2 + p3)) + b2own;

                // ---- RK4 bookkeeping (lane's comp only) ----
                if (e == 0)      acc = f;
                else if (e == 3) acc = acc + f;
                else             acc = fmaf(2.0f, f, acc);
                if (e < 3) {
                    const float cy = (e == 2) ? dtq : hdt;
                    ysg[lane] = fmaf(cy, f, hown);
                } else {
                    hown = fmaf(dt6, acc, hown);
                    ysg[lane] = hown;
                }
                __syncwarp();
            }
        }

        // ---- GRU cell: lane owns unit u = lane ----
        float gr = bihr, gz = bihz, gn = bihn;
#pragma unroll
        for (int mc = 0; mc < 8; mc++) {
            const float4 x4 = *(const float4*)(xsg + mc * 4);
            const float4 wr = *(const float4*)(&Wihc[lane * 108 +  0 + mc * 4]);
            const float4 wz = *(const float4*)(&Wihc[lane * 108 + 36 + mc * 4]);
            const float4 wn = *(const float4*)(&Wihc[lane * 108 + 72 + mc * 4]);
            gr = fmaf(x4.x, wr.x, gr); gr = fmaf(x4.y, wr.y, gr);
            gr = fmaf(x4.z, wr.z, gr); gr = fmaf(x4.w, wr.w, gr);
            gz = fmaf(x4.x, wz.x, gz); gz = fmaf(x4.y, wz.y, gz);
            gz = fmaf(x4.z, wz.z, gz); gz = fmaf(x4.w, wz.w, gz);
            gn = fmaf(x4.x, wn.x, gn); gn = fmaf(x4.y, wn.y, gn);
            gn = fmaf(x4.z, wn.z, gn); gn = fmaf(x4.w, wn.w, gn);
        }
        float qr = bhhr, qz = bhhz, qn = bhhn;
#pragma unroll
        for (int kc = 0; kc < 4; kc++) {
            const float4 h4 = *(const float4*)(ysg + kc * 4);
            const float4 wr = *(const float4*)(&Whhc[lane * 60 +  0 + kc * 4]);
            const float4 wz = *(const float4*)(&Whhc[lane * 60 + 20 + kc * 4]);
            const float4 wn = *(const float4*)(&Whhc[lane * 60 + 40 + kc * 4]);
            qr = fmaf(h4.x, wr.x, qr); qr = fmaf(h4.y, wr.y, qr);
            qr = fmaf(h4.z, wr.z, qr); qr = fmaf(h4.w, wr.w, qr);
            qz = fmaf(h4.x, wz.x, qz); qz = fmaf(h4.y, wz.y, qz);
            qz = fmaf(h4.z, wz.z, qz); qz = fmaf(h4.w, wz.w, qz);
            qn = fmaf(h4.x, wn.x, qn); qn = fmaf(h4.y, wn.y, qn);
            qn = fmaf(h4.z, wn.z, qn); qn = fmaf(h4.w, wn.w, qn);
        }
        const float r = fast_sig(gr + qr);
        const float z = fast_sig(gz + qz);
        const float n = fast_tanh(fmaf(r, qn, gn));
        const float hn = fmaf(z, hown - n, n);    // (1-z)*n + z*h
        hown = hn;

        // ---- output head: sum over the 16 lanes of the group ----
        float po = hn * woown;
        po += __shfl_xor_sync(FULLM, po, 8, 16);
        po += __shfl_xor_sync(FULLM, po, 4, 16);
        po += __shfl_xor_sync(FULLM, po, 2, 16);
        po += __shfl_xor_sync(FULLM, po, 1, 16);
        if (lane == 0) out[(size_t)i * BATCH + row] = po + bo;

        ysg[lane] = hn;                 // publish new hidden state
        __syncwarp();
    }
}

extern "C" void kernel_launch(void* const* d_in, const int* in_sizes, int n_in,
                              void* d_out, int out_size) {
    (void)in_sizes; (void)n_in; (void)out_size;
    const float* x    = (const float*)d_in[0];
    const float* t    = (const float*)d_in[1];
    const float* W1   = (const float*)d_in[2];
    const float* b1   = (const float*)d_in[3];
    const float* W2   = (const float*)d_in[4];
    const float* b2   = (const float*)d_in[5];
    const float* Wih  = (const float*)d_in[6];
    const float* bih  = (const float*)d_in[7];
    const float* Whh  = (const float*)d_in[8];
    const float* bhh  = (const float*)d_in[9];
    const float* Wout = (const float*)d_in[10];
    const float* bout = (const float*)d_in[11];
    float* out = (float*)d_out;

    dim3 grid(BATCH / ROWS_PER_BLK);   // 512 blocks, 8 rows each
    dim3 block(BLK);
    odernn_kernel<<<grid, block>>>(x, t, W1, b1, W2, b2, Wih, bih, Whh, bhh, Wout, bout, out);
}

// round 6
// speedup vs baseline: 2.3661x; 1.5913x over previous
#include <cuda_runtime.h>
#include <cstddef>

// ODE-RNN persistent kernel — shared-state + 2-row register blocking.
// T=500, B=4096, IN=32, HID=16, ODE_HIDDEN=50 (pad 64), RK4 x4.
// 16-lane group handles TWO rows; lane owns hidden comp c=lane (both rows) and
// ODE units 4c..4c+3. One weight load feeds both rows' FMAs.
// Warp = 2 groups = 4 rows. Block = 128 thr = 16 rows. Grid = 256.

#define T_STEPS 500
#define BATCH   4096
#define IN_DIM  32
#define HID     16
#define BLK     128

#define YPITCH  24
#define ZPITCH  72
#define XPITCH  72   // per row-PAIR: row A at 0, row B at 32

__device__ __forceinline__ float tanh_apx(float x) {
    float r;
    asm("tanh.approx.f32 %0, %1;" : "=f"(r) : "f"(x));
    return r;
}
__device__ __forceinline__ float sig_apx(float v) {   // sigmoid via tanh
    return fmaf(0.5f, tanh_apx(0.5f * v), 0.5f);
}

#define FULLM 0xffffffffu

__global__ void __launch_bounds__(BLK) odernn_kernel(
    const float* __restrict__ x,   const float* __restrict__ t,
    const float* __restrict__ W1,  const float* __restrict__ b1,
    const float* __restrict__ W2,  const float* __restrict__ b2,
    const float* __restrict__ Wih, const float* __restrict__ bih,
    const float* __restrict__ Whh, const float* __restrict__ bhh,
    const float* __restrict__ Wout, const float* __restrict__ bout,
    float* __restrict__ out)
{
    __shared__ float W1L[16 * 68];    // [k*68 + j] = W1[j][k] (j<50 else 0)
    __shared__ float b1L[64];
    __shared__ float W2c[16 * 68];    // [c*68 + j] = W2[c][j]
    __shared__ float Wihc[16 * 108];  // [u*108 + e*36 + m] = W_ih[e*16+u][m]
    __shared__ float Whhc[16 * 60];   // [u*60 + e*20 + k]  = W_hh[e*16+u][k]
    __shared__ float ys[16 * YPITCH]; // per-row state y/h
    __shared__ float zs[16 * ZPITCH]; // per-row layer-1 activations
    __shared__ float xs[8 * XPITCH];  // per-pair x staging
    __shared__ float ts[T_STEPS];

    const int tid = threadIdx.x;

    // ---- stage weights ----
    for (int idx = tid; idx < 16 * 68; idx += BLK) {
        int k = idx / 68, j = idx % 68;
        W1L[idx] = (j < 50) ? W1[j * HID + k] : 0.0f;
    }
    for (int idx = tid; idx < 64; idx += BLK)
        b1L[idx] = (idx < 50) ? b1[idx] : 0.0f;
    for (int idx = tid; idx < 16 * 68; idx += BLK) {
        int c = idx / 68, j = idx % 68;
        W2c[idx] = (j < 50) ? W2[c * 50 + j] : 0.0f;
    }
    for (int idx = tid; idx < 16 * 108; idx += BLK) {
        int u = idx / 108, r = idx % 108, e = r / 36, m = r % 36;
        Wihc[idx] = (m < 32) ? Wih[(e * HID + u) * IN_DIM + m] : 0.0f;
    }
    for (int idx = tid; idx < 16 * 60; idx += BLK) {
        int u = idx / 60, r = idx % 60, e = r / 20, k = r % 20;
        Whhc[idx] = (k < 16) ? Whh[(e * HID + u) * HID + k] : 0.0f;
    }
    for (int idx = tid; idx < T_STEPS; idx += BLK) ts[idx] = t[idx];

    const int lane = tid & 15;            // comp / unit owned
    const int g    = (tid >> 4) & 1;      // group within warp
    const int w    = tid >> 5;            // warp within block
    const int pair = w * 2 + g;           // 0..7
    const int slotA = pair * 2, slotB = pair * 2 + 1;
    const int rowA = blockIdx.x * 16 + slotA;
    const int rowB = rowA + 1;

    float* const ysA = ys + slotA * YPITCH;
    float* const ysB = ys + slotB * YPITCH;
    float* const zsA = zs + slotA * ZPITCH;
    float* const zsB = zs + slotB * ZPITCH;
    float* const xp  = xs + pair * XPITCH;

    // ---- per-lane constants ----
    const float b2own = b2[lane];
    const float woown = Wout[lane];
    const float bo    = bout[0];
    const float bihr = bih[lane], bihz = bih[16 + lane], bihn = bih[32 + lane];
    const float bhhr = bhh[lane], bhhz = bhh[16 + lane], bhhn = bhh[32 + lane];

    ysA[lane] = 0.0f;
    ysB[lane] = 0.0f;
    float hownA = 0.0f, hownB = 0.0f;
    __syncthreads();

    const float4 b1own = *(const float4*)(b1L + lane * 4);

    // x staging: lane<8 covers rowA, lane>=8 covers rowB (16B chunks)
    const int xhalf = lane >> 3;
    const int xoff  = (lane & 7) * 4;
    const float* xsrcA = x + (size_t)rowA * IN_DIM;   // + i*BATCH*IN_DIM per step
    const float* xsrc  = (xhalf ? (x + (size_t)rowB * IN_DIM) : (x + (size_t)rowA * IN_DIM)) + xoff;

#pragma unroll 1
    for (int i = 0; i < T_STEPS - 1; ++i) {
        // stage this step's x (consumed by GRU after the eval syncs)
        const float4 gx = __ldg((const float4*)(xsrc + (size_t)i * BATCH * IN_DIM));
        *(float4*)(xp + xhalf * 32 + xoff) = gx;

        const float dtq = (ts[i + 1] - ts[i]) * 0.25f;
        const float hdt = 0.5f * dtq;
        const float dt6 = dtq * (1.0f / 6.0f);

        float accA = 0.0f, accB = 0.0f;
#pragma unroll 1
        for (int ss = 0; ss < 4; ss++) {
#pragma unroll 1
            for (int e = 0; e < 4; e++) {
                // ---- read y for both rows (broadcast) ----
                float ya[16], yb[16];
                *(float4*)(ya + 0)  = *(const float4*)(ysA + 0);
                *(float4*)(ya + 4)  = *(const float4*)(ysA + 4);
                *(float4*)(ya + 8)  = *(const float4*)(ysA + 8);
                *(float4*)(ya + 12) = *(const float4*)(ysA + 12);
                *(float4*)(yb + 0)  = *(const float4*)(ysB + 0);
                *(float4*)(yb + 4)  = *(const float4*)(ysB + 4);
                *(float4*)(yb + 8)  = *(const float4*)(ysB + 8);
                *(float4*)(yb + 12) = *(const float4*)(ysB + 12);

                // ---- layer 1: lane's 4 units, both rows ----
                float4 aA = b1own, aB = b1own;
#pragma unroll
                for (int k = 0; k < 16; k++) {
                    const float4 wq = *(const float4*)(&W1L[k * 68 + lane * 4]);
                    const float yAk = ya[k], yBk = yb[k];
                    aA.x = fmaf(yAk, wq.x, aA.x); aA.y = fmaf(yAk, wq.y, aA.y);
                    aA.z = fmaf(yAk, wq.z, aA.z); aA.w = fmaf(yAk, wq.w, aA.w);
                    aB.x = fmaf(yBk, wq.x, aB.x); aB.y = fmaf(yBk, wq.y, aB.y);
                    aB.z = fmaf(yBk, wq.z, aB.z); aB.w = fmaf(yBk, wq.w, aB.w);
                }
                float4 zA, zB;
                zA.x = tanh_apx(aA.x); zA.y = tanh_apx(aA.y);
                zA.z = tanh_apx(aA.z); zA.w = tanh_apx(aA.w);
                zB.x = tanh_apx(aB.x); zB.y = tanh_apx(aB.y);
                zB.z = tanh_apx(aB.z); zB.w = tanh_apx(aB.w);
                *(float4*)(zsA + lane * 4) = zA;
                *(float4*)(zsB + lane * 4) = zB;
                __syncwarp();

                // ---- layer 2: lane's comp over all 64 z, both rows ----
                float4 pA = make_float4(0.f, 0.f, 0.f, 0.f), pB = pA;
#pragma unroll
                for (int jc = 0; jc < 16; jc++) {
                    const float4 wq = *(const float4*)(&W2c[lane * 68 + jc * 4]);
                    const float4 zA4 = *(const float4*)(zsA + jc * 4);
                    const float4 zB4 = *(const float4*)(zsB + jc * 4);
                    pA.x = fmaf(zA4.x, wq.x, pA.x); pA.y = fmaf(zA4.y, wq.y, pA.y);
                    pA.z = fmaf(zA4.z, wq.z, pA.z); pA.w = fmaf(zA4.w, wq.w, pA.w);
                    pB.x = fmaf(zB4.x, wq.x, pB.x); pB.y = fmaf(zB4.y, wq.y, pB.y);
                    pB.z = fmaf(zB4.z, wq.z, pB.z); pB.w = fmaf(zB4.w, wq.w, pB.w);
                }
                const float fA = ((pA.x + pA.y) + (pA.z + pA.w)) + b2own;
                const float fB = ((pB.x + pB.y) + (pB.z + pB.w)) + b2own;

                // ---- RK4 bookkeeping (own comp only) ----
                if (e == 0)      { accA = fA;                  accB = fB; }
                else if (e == 3) { accA += fA;                 accB += fB; }
                else             { accA = fmaf(2.f, fA, accA); accB = fmaf(2.f, fB, accB); }
                if (e < 3) {
                    const float cy = (e == 2) ? dtq : hdt;
                    ysA[lane] = fmaf(cy, fA, hownA);
                    ysB[lane] = fmaf(cy, fB, hownB);
                } else {
                    hownA = fmaf(dt6, accA, hownA);
                    hownB = fmaf(dt6, accB, hownB);
                    ysA[lane] = hownA;
                    ysB[lane] = hownB;
                }
                __syncwarp();
            }
        }

        // ---- GRU cell: lane owns unit u=lane for both rows ----
        float grA = bihr, gzA = bihz, gnA = bihn;
        float grB = bihr, gzB = bihz, gnB = bihn;
#pragma unroll
        for (int mc = 0; mc < 8; mc++) {
            const float4 xA4 = *(const float4*)(xp + mc * 4);
            const float4 xB4 = *(const float4*)(xp + 32 + mc * 4);
            const float4 wr = *(const float4*)(&Wihc[lane * 108 +  0 + mc * 4]);
            const float4 wz = *(const float4*)(&Wihc[lane * 108 + 36 + mc * 4]);
            const float4 wn = *(const float4*)(&Wihc[lane * 108 + 72 + mc * 4]);
            grA = fmaf(xA4.x, wr.x, grA); grA = fmaf(xA4.y, wr.y, grA);
            grA = fmaf(xA4.z, wr.z, grA); grA = fmaf(xA4.w, wr.w, grA);
            gzA = fmaf(xA4.x, wz.x, gzA); gzA = fmaf(xA4.y, wz.y, gzA);
            gzA = fmaf(xA4.z, wz.z, gzA); gzA = fmaf(xA4.w, wz.w, gzA);
            gnA = fmaf(xA4.x, wn.x, gnA); gnA = fmaf(xA4.y, wn.y, gnA);
            gnA = fmaf(xA4.z, wn.z, gnA); gnA = fmaf(xA4.w, wn.w, gnA);
            grB = fmaf(xB4.x, wr.x, grB); grB = fmaf(xB4.y, wr.y, grB);
            grB = fmaf(xB4.z, wr.z, grB); grB = fmaf(xB4.w, wr.w, grB);
            gzB = fmaf(xB4.x, wz.x, gzB); gzB = fmaf(xB4.y, wz.y, gzB);
            gzB = fmaf(xB4.z, wz.z, gzB); gzB = fmaf(xB4.w, wz.w, gzB);
            gnB = fmaf(xB4.x, wn.x, gnB); gnB = fmaf(xB4.y, wn.y, gnB);
            gnB = fmaf(xB4.z, wn.z, gnB); gnB = fmaf(xB4.w, wn.w, gnB);
        }
        float qrA = bhhr, qzA = bhhz, qnA = bhhn;
        float qrB = bhhr, qzB = bhhz, qnB = bhhn;
#pragma unroll
        for (int kc = 0; kc < 4; kc++) {
            const float4 hA4 = *(const float4*)(ysA + kc * 4);
            const float4 hB4 = *(const float4*)(ysB + kc * 4);
            const float4 wr = *(const float4*)(&Whhc[lane * 60 +  0 + kc * 4]);
            const float4 wz = *(const float4*)(&Whhc[lane * 60 + 20 + kc * 4]);
            const float4 wn = *(const float4*)(&Whhc[lane * 60 + 40 + kc * 4]);
            qrA = fmaf(hA4.x, wr.x, qrA); qrA = fmaf(hA4.y, wr.y, qrA);
            qrA = fmaf(hA4.z, wr.z, qrA); qrA = fmaf(hA4.w, wr.w, qrA);
            qzA = fmaf(hA4.x, wz.x, qzA); qzA = fmaf(hA4.y, wz.y, qzA);
            qzA = fmaf(hA4.z, wz.z, qzA); qzA = fmaf(hA4.w, wz.w, qzA);
            qnA = fmaf(hA4.x, wn.x, qnA); qnA = fmaf(hA4.y, wn.y, qnA);
            qnA = fmaf(hA4.z, wn.z, qnA); qnA = fmaf(hA4.w, wn.w, qnA);
            qrB = fmaf(hB4.x, wr.x, qrB); qrB = fmaf(hB4.y, wr.y, qrB);
            qrB = fmaf(hB4.z, wr.z, qrB); qrB = fmaf(hB4.w, wr.w, qrB);
            qzB = fmaf(hB4.x, wz.x, qzB); qzB = fmaf(hB4.y, wz.y, qzB);
            qzB = fmaf(hB4.z, wz.z, qzB); qzB = fmaf(hB4.w, wz.w, qzB);
            qnB = fmaf(hB4.x, wn.x, qnB); qnB = fmaf(hB4.y, wn.y, qnB);
            qnB = fmaf(hB4.z, wn.z, qnB); qnB = fmaf(hB4.w, wn.w, qnB);
        }
        const float rA = sig_apx(grA + qrA);
        const float zA_ = sig_apx(gzA + qzA);
        const float nA = tanh_apx(fmaf(rA, qnA, gnA));
        const float hnA = fmaf(zA_, hownA - nA, nA);
        const float rB = sig_apx(grB + qrB);
        const float zB_ = sig_apx(gzB + qzB);
        const float nB = tanh_apx(fmaf(rB, qnB, gnB));
        const float hnB = fmaf(zB_, hownB - nB, nB);
        hownA = hnA; hownB = hnB;

        // ---- output head (reduce over the 16 lanes of the group) ----
        float poA = hnA * woown, poB = hnB * woown;
        poA += __shfl_xor_sync(FULLM, poA, 1, 16);
        poA += __shfl_xor_sync(FULLM, poA, 2, 16);
        poA += __shfl_xor_sync(FULLM, poA, 4, 16);
        poA += __shfl_xor_sync(FULLM, poA, 8, 16);
        poB += __shfl_xor_sync(FULLM, poB, 1, 16);
        poB += __shfl_xor_sync(FULLM, poB, 2, 16);
        poB += __shfl_xor_sync(FULLM, poB, 4, 16);
        poB += __shfl_xor_sync(FULLM, poB, 8, 16);
        if (lane == 0) {
            out[(size_t)i * BATCH + rowA] = poA + bo;
            out[(size_t)i * BATCH + rowB] = poB + bo;
        }

        // ---- publish new hidden state ----
        ysA[lane] = hnA;
        ysB[lane] = hnB;
        __syncwarp();
    }
    (void)xsrcA;
}

extern "C" void kernel_launch(void* const* d_in, const int* in_sizes, int n_in,
                              void* d_out, int out_size) {
    (void)in_sizes; (void)n_in; (void)out_size;
    const float* x    = (const float*)d_in[0];
    const float* t    = (const float*)d_in[1];
    const float* W1   = (const float*)d_in[2];
    const float* b1   = (const float*)d_in[3];
    const float* W2   = (const float*)d_in[4];
    const float* b2   = (const float*)d_in[5];
    const float* Wih  = (const float*)d_in[6];
    const float* bih  = (const float*)d_in[7];
    const float* Whh  = (const float*)d_in[8];
    const float* bhh  = (const float*)d_in[9];
    const float* Wout = (const float*)d_in[10];
    const float* bout = (const float*)d_in[11];
    float* out = (float*)d_out;

    dim3 grid(BATCH / 16);   // 256 blocks, 16 rows each
    dim3 block(BLK);
    odernn_kernel<<<grid, block>>>(x, t, W1, b1, W2, b2, Wih, bih, Whh, bhh, Wout, bout, out);
}

// round 7
// speedup vs baseline: 3.1641x; 1.3373x over previous
#include <cuda_runtime.h>
#include <cstddef>

// ODE-RNN persistent kernel — W2-in-registers + shuffle reduce-scatter.
// T=500, B=4096, IN=32, HID=16, ODE_HIDDEN=50 (pad 64), RK4 x4.
// 16-lane group handles TWO rows (register blocked); lane owns ODE units 4c..4c+3
// (layer-1 + its W2 slice in regs) and hidden comp c (RK4 state, GRU unit).
// Layer-2 partials reduced across lanes with xor shuffles — no z smem round-trip.
// Warp = 2 groups = 4 rows. Block = 128 thr = 16 rows. Grid = 256.

#define T_STEPS 500
#define BATCH   4096
#define IN_DIM  32
#define HID     16
#define BLK     128

#define YPITCH  24
#define XPITCH  72   // per row-PAIR: row A at 0, row B at 32

__device__ __forceinline__ float tanh_apx(float x) {
    float r;
    asm("tanh.approx.f32 %0, %1;" : "=f"(r) : "f"(x));
    return r;
}
__device__ __forceinline__ float sig_apx(float v) {
    return fmaf(0.5f, tanh_apx(0.5f * v), 0.5f);
}

#define FULLM 0xffffffffu

// reduce-scatter over 16 lanes: v[16] per-lane partials -> returns full sum of comp 'lane'
__device__ __forceinline__ float rs16(const float (&v)[16], int lane) {
    const bool b8 = (lane & 8) != 0;
    float t8[8];
#pragma unroll
    for (int r = 0; r < 8; r++) {
        const float send = b8 ? v[r] : v[r + 8];
        const float keep = b8 ? v[r + 8] : v[r];
        t8[r] = keep + __shfl_xor_sync(FULLM, send, 8, 16);
    }
    const bool b4 = (lane & 4) != 0;
    float t4[4];
#pragma unroll
    for (int r = 0; r < 4; r++) {
        const float send = b4 ? t8[r] : t8[r + 4];
        const float keep = b4 ? t8[r + 4] : t8[r];
        t4[r] = keep + __shfl_xor_sync(FULLM, send, 4, 16);
    }
    const bool b2 = (lane & 2) != 0;
    float t2[2];
#pragma unroll
    for (int r = 0; r < 2; r++) {
        const float send = b2 ? t4[r] : t4[r + 2];
        const float keep = b2 ? t4[r + 2] : t4[r];
        t2[r] = keep + __shfl_xor_sync(FULLM, send, 2, 16);
    }
    const bool b1 = (lane & 1) != 0;
    const float send = b1 ? t2[0] : t2[1];
    const float keep = b1 ? t2[1] : t2[0];
    return keep + __shfl_xor_sync(FULLM, send, 1, 16);
}

__global__ void __launch_bounds__(BLK) odernn_kernel(
    const float* __restrict__ x,   const float* __restrict__ t,
    const float* __restrict__ W1,  const float* __restrict__ b1,
    const float* __restrict__ W2,  const float* __restrict__ b2,
    const float* __restrict__ Wih, const float* __restrict__ bih,
    const float* __restrict__ Whh, const float* __restrict__ bhh,
    const float* __restrict__ Wout, const float* __restrict__ bout,
    float* __restrict__ out)
{
    __shared__ float W1L[16 * 68];    // [k*68 + j] = W1[j][k] (j<50 else 0)
    __shared__ float b1L[64];
    __shared__ float Wihc[16 * 108];  // [u*108 + e*36 + m] = W_ih[e*16+u][m]
    __shared__ float Whhc[16 * 60];   // [u*60 + e*20 + k]  = W_hh[e*16+u][k]
    __shared__ float ys[16 * YPITCH]; // per-row state y/h
    __shared__ float xs[8 * XPITCH];  // per-pair x staging
    __shared__ float ts[T_STEPS];

    const int tid = threadIdx.x;

    // ---- stage shared weights ----
    for (int idx = tid; idx < 16 * 68; idx += BLK) {
        int k = idx / 68, j = idx % 68;
        W1L[idx] = (j < 50) ? W1[j * HID + k] : 0.0f;
    }
    for (int idx = tid; idx < 64; idx += BLK)
        b1L[idx] = (idx < 50) ? b1[idx] : 0.0f;
    for (int idx = tid; idx < 16 * 108; idx += BLK) {
        int u = idx / 108, r = idx % 108, e = r / 36, m = r % 36;
        Wihc[idx] = (m < 32) ? Wih[(e * HID + u) * IN_DIM + m] : 0.0f;
    }
    for (int idx = tid; idx < 16 * 60; idx += BLK) {
        int u = idx / 60, r = idx % 60, e = r / 20, k = r % 20;
        Whhc[idx] = (k < 16) ? Whh[(e * HID + u) * HID + k] : 0.0f;
    }
    for (int idx = tid; idx < T_STEPS; idx += BLK) ts[idx] = t[idx];

    const int lane = tid & 15;
    const int g    = (tid >> 4) & 1;
    const int w    = tid >> 5;
    const int pair = w * 2 + g;           // 0..7
    const int slotA = pair * 2, slotB = pair * 2 + 1;
    const int rowA = blockIdx.x * 16 + slotA;
    const int rowB = rowA + 1;

    float* const ysA = ys + slotA * YPITCH;
    float* const ysB = ys + slotB * YPITCH;
    float* const xp  = xs + pair * XPITCH;

    // ---- W2 register slice: w2r[jj*16+i] = W2[i][4*lane+jj] ----
    float w2r[64];
#pragma unroll
    for (int jj = 0; jj < 4; jj++) {
        const int j = 4 * lane + jj;
#pragma unroll
        for (int ii = 0; ii < 16; ii++)
            w2r[jj * 16 + ii] = (j < 50) ? __ldg(&W2[ii * 50 + j]) : 0.0f;
    }

    // ---- per-lane constants ----
    const float b2own = b2[lane];
    const float woown = Wout[lane];
    const float bo    = bout[0];
    const float bihr = bih[lane], bihz = bih[16 + lane], bihn = bih[32 + lane];
    const float bhhr = bhh[lane], bhhz = bhh[16 + lane], bhhn = bhh[32 + lane];

    ysA[lane] = 0.0f;
    ysB[lane] = 0.0f;
    float hownA = 0.0f, hownB = 0.0f;
    __syncthreads();

    const float4 b1own = *(const float4*)(b1L + lane * 4);

    const int xhalf = lane >> 3;
    const int xoff  = (lane & 7) * 4;
    const float* xsrc = (xhalf ? (x + (size_t)rowB * IN_DIM) : (x + (size_t)rowA * IN_DIM)) + xoff;

#pragma unroll 1
    for (int i = 0; i < T_STEPS - 1; ++i) {
        const float4 gx = __ldg((const float4*)(xsrc + (size_t)i * BATCH * IN_DIM));
        *(float4*)(xp + xhalf * 32 + xoff) = gx;

        const float dtq = (ts[i + 1] - ts[i]) * 0.25f;
        const float hdt = 0.5f * dtq;
        const float dt6 = dtq * (1.0f / 6.0f);

        float accA = 0.0f, accB = 0.0f;
#pragma unroll 1
        for (int ss = 0; ss < 4; ss++) {
#pragma unroll 1
            for (int e = 0; e < 4; e++) {
                // ---- read y for both rows (broadcast LDS) ----
                float ya[16], yb[16];
                *(float4*)(ya + 0)  = *(const float4*)(ysA + 0);
                *(float4*)(ya + 4)  = *(const float4*)(ysA + 4);
                *(float4*)(ya + 8)  = *(const float4*)(ysA + 8);
                *(float4*)(ya + 12) = *(const float4*)(ysA + 12);
                *(float4*)(yb + 0)  = *(const float4*)(ysB + 0);
                *(float4*)(yb + 4)  = *(const float4*)(ysB + 4);
                *(float4*)(yb + 8)  = *(const float4*)(ysB + 8);
                *(float4*)(yb + 12) = *(const float4*)(ysB + 12);
                __syncwarp();   // all lanes captured y before later overwrite

                // ---- layer 1: lane's 4 units, both rows ----
                float4 aA = b1own, aB = b1own;
#pragma unroll
                for (int k = 0; k < 16; k++) {
                    const float4 wq = *(const float4*)(&W1L[k * 68 + lane * 4]);
                    const float yAk = ya[k], yBk = yb[k];
                    aA.x = fmaf(yAk, wq.x, aA.x); aA.y = fmaf(yAk, wq.y, aA.y);
                    aA.z = fmaf(yAk, wq.z, aA.z); aA.w = fmaf(yAk, wq.w, aA.w);
                    aB.x = fmaf(yBk, wq.x, aB.x); aB.y = fmaf(yBk, wq.y, aB.y);
                    aB.z = fmaf(yBk, wq.z, aB.z); aB.w = fmaf(yBk, wq.w, aB.w);
                }
                float4 zA, zB;
                zA.x = tanh_apx(aA.x); zA.y = tanh_apx(aA.y);
                zA.z = tanh_apx(aA.z); zA.w = tanh_apx(aA.w);
                zB.x = tanh_apx(aB.x); zB.y = tanh_apx(aB.y);
                zB.z = tanh_apx(aB.z); zB.w = tanh_apx(aB.w);

                // ---- layer 2: per-lane partials with register W2 slice ----
                float pf[16];
#pragma unroll
                for (int ii = 0; ii < 16; ii++)
                    pf[ii] = fmaf(zA.x, w2r[ii],
                             fmaf(zA.y, w2r[16 + ii],
                             fmaf(zA.z, w2r[32 + ii], zA.w * w2r[48 + ii])));
                const float fA = rs16(pf, lane) + b2own;
#pragma unroll
                for (int ii = 0; ii < 16; ii++)
                    pf[ii] = fmaf(zB.x, w2r[ii],
                             fmaf(zB.y, w2r[16 + ii],
                             fmaf(zB.z, w2r[32 + ii], zB.w * w2r[48 + ii])));
                const float fB = rs16(pf, lane) + b2own;

                // ---- RK4 bookkeeping (own comp only) ----
                if (e == 0)      { accA = fA;                  accB = fB; }
                else if (e == 3) { accA += fA;                 accB += fB; }
                else             { accA = fmaf(2.f, fA, accA); accB = fmaf(2.f, fB, accB); }
                if (e < 3) {
                    const float cy = (e == 2) ? dtq : hdt;
                    ysA[lane] = fmaf(cy, fA, hownA);
                    ysB[lane] = fmaf(cy, fB, hownB);
                } else {
                    hownA = fmaf(dt6, accA, hownA);
                    hownB = fmaf(dt6, accB, hownB);
                    ysA[lane] = hownA;
                    ysB[lane] = hownB;
                }
                __syncwarp();
            }
        }

        // ---- GRU cell: lane owns unit u=lane for both rows ----
        float grA = bihr, gzA = bihz, gnA = bihn;
        float grB = bihr, gzB = bihz, gnB = bihn;
#pragma unroll
        for (int mc = 0; mc < 8; mc++) {
            const float4 xA4 = *(const float4*)(xp + mc * 4);
            const float4 xB4 = *(const float4*)(xp + 32 + mc * 4);
            const float4 wr = *(const float4*)(&Wihc[lane * 108 +  0 + mc * 4]);
            const float4 wz = *(const float4*)(&Wihc[lane * 108 + 36 + mc * 4]);
            const float4 wn = *(const float4*)(&Wihc[lane * 108 + 72 + mc * 4]);
            grA = fmaf(xA4.x, wr.x, grA); grA = fmaf(xA4.y, wr.y, grA);
            grA = fmaf(xA4.z, wr.z, grA); grA = fmaf(xA4.w, wr.w, grA);
            gzA = fmaf(xA4.x, wz.x, gzA); gzA = fmaf(xA4.y, wz.y, gzA);
            gzA = fmaf(xA4.z, wz.z, gzA); gzA = fmaf(xA4.w, wz.w, gzA);
            gnA = fmaf(xA4.x, wn.x, gnA); gnA = fmaf(xA4.y, wn.y, gnA);
            gnA = fmaf(xA4.z, wn.z, gnA); gnA = fmaf(xA4.w, wn.w, gnA);
            grB = fmaf(xB4.x, wr.x, grB); grB = fmaf(xB4.y, wr.y, grB);
            grB = fmaf(xB4.z, wr.z, grB); grB = fmaf(xB4.w, wr.w, grB);
            gzB = fmaf(xB4.x, wz.x, gzB); gzB = fmaf(xB4.y, wz.y, gzB);
            gzB = fmaf(xB4.z, wz.z, gzB); gzB = fmaf(xB4.w, wz.w, gzB);
            gnB = fmaf(xB4.x, wn.x, gnB); gnB = fmaf(xB4.y, wn.y, gnB);
            gnB = fmaf(xB4.z, wn.z, gnB); gnB = fmaf(xB4.w, wn.w, gnB);
        }
        float qrA = bhhr, qzA = bhhz, qnA = bhhn;
        float qrB = bhhr, qzB = bhhz, qnB = bhhn;
#pragma unroll
        for (int kc = 0; kc < 4; kc++) {
            const float4 hA4 = *(const float4*)(ysA + kc * 4);
            const float4 hB4 = *(const float4*)(ysB + kc * 4);
            const float4 wr = *(const float4*)(&Whhc[lane * 60 +  0 + kc * 4]);
            const float4 wz = *(const float4*)(&Whhc[lane * 60 + 20 + kc * 4]);
            const float4 wn = *(const float4*)(&Whhc[lane * 60 + 40 + kc * 4]);
            qrA = fmaf(hA4.x, wr.x, qrA); qrA = fmaf(hA4.y, wr.y, qrA);
            qrA = fmaf(hA4.z, wr.z, qrA); qrA = fmaf(hA4.w, wr.w, qrA);
            qzA = fmaf(hA4.x, wz.x, qzA); qzA = fmaf(hA4.y, wz.y, qzA);
            qzA = fmaf(hA4.z, wz.z, qzA); qzA = fmaf(hA4.w, wz.w, qzA);
            qnA = fmaf(hA4.x, wn.x, qnA); qnA = fmaf(hA4.y, wn.y, qnA);
            qnA = fmaf(hA4.z, wn.z, qnA); qnA = fmaf(hA4.w, wn.w, qnA);
            qrB = fmaf(hB4.x, wr.x, qrB); qrB = fmaf(hB4.y, wr.y, qrB);
            qrB = fmaf(hB4.z, wr.z, qrB); qrB = fmaf(hB4.w, wr.w, qrB);
            qzB = fmaf(hB4.x, wz.x, qzB); qzB = fmaf(hB4.y, wz.y, qzB);
            qzB = fmaf(hB4.z, wz.z, qzB); qzB = fmaf(hB4.w, wz.w, qzB);
            qnB = fmaf(hB4.x, wn.x, qnB); qnB = fmaf(hB4.y, wn.y, qnB);
            qnB = fmaf(hB4.z, wn.z, qnB); qnB = fmaf(hB4.w, wn.w, qnB);
        }
        const float rA = sig_apx(grA + qrA);
        const float zA_ = sig_apx(gzA + qzA);
        const float nA = tanh_apx(fmaf(rA, qnA, gnA));
        const float hnA = fmaf(zA_, hownA - nA, nA);
        const float rB = sig_apx(grB + qrB);
        const float zB_ = sig_apx(gzB + qzB);
        const float nB = tanh_apx(fmaf(rB, qnB, gnB));
        const float hnB = fmaf(zB_, hownB - nB, nB);
        hownA = hnA; hownB = hnB;

        // ---- output head ----
        float poA = hnA * woown, poB = hnB * woown;
        poA += __shfl_xor_sync(FULLM, poA, 1, 16);
        poA += __shfl_xor_sync(FULLM, poA, 2, 16);
        poA += __shfl_xor_sync(FULLM, poA, 4, 16);
        poA += __shfl_xor_sync(FULLM, poA, 8, 16);
        poB += __shfl_xor_sync(FULLM, poB, 1, 16);
        poB += __shfl_xor_sync(FULLM, poB, 2, 16);
        poB += __shfl_xor_sync(FULLM, poB, 4, 16);
        poB += __shfl_xor_sync(FULLM, poB, 8, 16);
        if (lane == 0) {
            out[(size_t)i * BATCH + rowA] = poA + bo;
            out[(size_t)i * BATCH + rowB] = poB + bo;
        }

        // ---- publish new hidden state ----
        ysA[lane] = hnA;
        ysB[lane] = hnB;
        __syncwarp();
    }
}

extern "C" void kernel_launch(void* const* d_in, const int* in_sizes, int n_in,
                              void* d_out, int out_size) {
    (void)in_sizes; (void)n_in; (void)out_size;
    const float* x    = (const float*)d_in[0];
    const float* t    = (const float*)d_in[1];
    const float* W1   = (const float*)d_in[2];
    const float* b1   = (const float*)d_in[3];
    const float* W2   = (const float*)d_in[4];
    const float* b2   = (const float*)d_in[5];
    const float* Wih  = (const float*)d_in[6];
    const float* bih  = (const float*)d_in[7];
    const float* Whh  = (const float*)d_in[8];
    const float* bhh  = (const float*)d_in[9];
    const float* Wout = (const float*)d_in[10];
    const float* bout = (const float*)d_in[11];
    float* out = (float*)d_out;

    dim3 grid(BATCH / 16);
    dim3 block(BLK);
    odernn_kernel<<<grid, block>>>(x, t, W1, b1, W2, b2, Wih, bih, Whh, bhh, Wout, bout, out);
}